// round 3
// baseline (speedup 1.0000x reference)
#include <cuda_runtime.h>

// Problem constants
#define BB   16
#define DIN  512
#define DH   2048
#define DOUT 512

// Device-global scratch (no allocations allowed in kernel_launch)
__device__ float g_W1T[DH * DIN];   // 4 MB: W1 transposed -> W1T[h][i]
__device__ int   g_act[BB * DH];    // compacted active h indices per batch (sorted)
__device__ int   g_cnt[BB];         // active count per batch

// ---------------------------------------------------------------------------
// Kernel 1: zero the whole output (block-diagonal -> off-diagonal stays 0)
// ---------------------------------------------------------------------------
__global__ void zero_kernel(float4* __restrict__ out, int n4) {
    int idx = blockIdx.x * blockDim.x + threadIdx.x;
    if (idx < n4) out[idx] = make_float4(0.f, 0.f, 0.f, 0.f);
}

// ---------------------------------------------------------------------------
// Kernel 2: per-batch pre-activations, ReLU mask, deterministic compaction.
// One block per b, 256 threads; thread t owns h in [t*8, t*8+8) so the
// compacted index list comes out sorted (deterministic GEMM sum order).
// ---------------------------------------------------------------------------
__global__ void __launch_bounds__(256)
mask_compact_kernel(const float* __restrict__ x,
                    const float* __restrict__ W1,
                    const float* __restrict__ b1) {
    int b = blockIdx.x;
    int t = threadIdx.x;

    __shared__ float xs[DIN];
    for (int i = t; i < DIN; i += 256) xs[i] = x[b * DIN + i];
    __syncthreads();

    const int h0 = t * 8;
    float acc[8];
#pragma unroll
    for (int u = 0; u < 8; u++) acc[u] = b1[h0 + u];

    // Each thread reads a contiguous 32B (2x float4) slice of every W1 row:
    // lane t covers bytes [t*32, t*32+32) -> fully coalesced per warp.
    const float4* wrow = reinterpret_cast<const float4*>(W1 + h0);
    for (int i = 0; i < DIN; i++) {
        float  xv = xs[i];
        float4 w0 = wrow[0];
        float4 w1 = wrow[1];
        wrow += DH / 4;
        acc[0] += xv * w0.x; acc[1] += xv * w0.y;
        acc[2] += xv * w0.z; acc[3] += xv * w0.w;
        acc[4] += xv * w1.x; acc[5] += xv * w1.y;
        acc[6] += xv * w1.z; acc[7] += xv * w1.w;
    }

    int flags = 0, cnt = 0;
#pragma unroll
    for (int u = 0; u < 8; u++) {
        if (acc[u] > 0.f) { flags |= (1 << u); cnt++; }
    }

    // Block-wide inclusive scan (Hillis-Steele) of per-thread counts
    __shared__ int cnts[256];
    cnts[t] = cnt;
    __syncthreads();
    for (int off = 1; off < 256; off <<= 1) {
        int v   = cnts[t];
        int add = (t >= off) ? cnts[t - off] : 0;
        __syncthreads();
        cnts[t] = v + add;
        __syncthreads();
    }

    int pos = cnts[t] - cnt;  // exclusive prefix
#pragma unroll
    for (int u = 0; u < 8; u++) {
        if (flags & (1 << u)) g_act[b * DH + (pos++)] = h0 + u;
    }
    if (t == 255) g_cnt[b] = cnts[255];
}

// ---------------------------------------------------------------------------
// Kernel 3: transpose W1 [DIN, DH] -> g_W1T [DH, DIN] (coalesced gathers later)
// ---------------------------------------------------------------------------
__global__ void transpose_kernel(const float* __restrict__ W1) {
    __shared__ float tile[32][33];
    int h0 = blockIdx.x * 32;
    int i0 = blockIdx.y * 32;
    int tx = threadIdx.x, ty = threadIdx.y;  // 32 x 8
#pragma unroll
    for (int r = 0; r < 32; r += 8)
        tile[ty + r][tx] = W1[(i0 + ty + r) * DH + h0 + tx];
    __syncthreads();
#pragma unroll
    for (int r = 0; r < 32; r += 8)
        g_W1T[(h0 + ty + r) * DIN + i0 + tx] = tile[tx][ty + r];
}

// ---------------------------------------------------------------------------
// Kernel 4: batched compacted GEMM.
//   J[b, o, b, i] = sum_j W2[act[j], o] * W1T[act[j], i]    (j < cnt[b])
// 64x64 output tile per block, 4x4 microtile per thread, K-tile = 16.
// Grid: (i-tiles=8, o-tiles=8, b=16), 256 threads.
// ---------------------------------------------------------------------------
__global__ void __launch_bounds__(256)
gemm_kernel(const float* __restrict__ W2, float* __restrict__ out) {
    int b      = blockIdx.z;
    int tile_o = blockIdx.y * 64;
    int tile_i = blockIdx.x * 64;
    int cnt    = g_cnt[b];
    const int* __restrict__ act = g_act + b * DH;

    __shared__ float As[16][64];  // W2 gathered rows  (k x o)
    __shared__ float Bs[16][64];  // W1T gathered rows (k x i)

    int t  = threadIdx.x;
    int tx = t & 15;   // i direction
    int ty = t >> 4;   // o direction

    float c[4][4] = {};

    for (int kt = 0; kt < cnt; kt += 16) {
        // Fill both tiles: 1024 elems each, 4 per thread
#pragma unroll
        for (int p = 0; p < 4; p++) {
            int e   = t + p * 256;
            int row = e >> 6;
            int col = e & 63;
            int j   = kt + row;
            float av = 0.f, bv = 0.f;
            if (j < cnt) {
                int h = act[j];
                av = W2[h * DOUT + tile_o + col];
                bv = g_W1T[h * DIN + tile_i + col];
            }
            As[row][col] = av;
            Bs[row][col] = bv;
        }
        __syncthreads();

#pragma unroll
        for (int k = 0; k < 16; k++) {
            float4 a = *reinterpret_cast<const float4*>(&As[k][ty * 4]);
            float4 v = *reinterpret_cast<const float4*>(&Bs[k][tx * 4]);
            float ar[4] = {a.x, a.y, a.z, a.w};
            float br[4] = {v.x, v.y, v.z, v.w};
#pragma unroll
            for (int r = 0; r < 4; r++)
#pragma unroll
                for (int s = 0; s < 4; s++)
                    c[r][s] += ar[r] * br[s];
        }
        __syncthreads();
    }

    // Epilogue: write diagonal block J[b, o, b, i]
#pragma unroll
    for (int r = 0; r < 4; r++) {
        int o = tile_o + ty * 4 + r;
        size_t base = ((size_t)((b * DOUT + o) * BB + b)) * DIN + tile_i + tx * 4;
        *reinterpret_cast<float4*>(&out[base]) =
            make_float4(c[r][0], c[r][1], c[r][2], c[r][3]);
    }
}

// ---------------------------------------------------------------------------
// Launch
// ---------------------------------------------------------------------------
extern "C" void kernel_launch(void* const* d_in, const int* in_sizes, int n_in,
                              void* d_out, int out_size) {
    const float* x  = (const float*)d_in[0];
    const float* W1 = (const float*)d_in[1];
    const float* b1 = (const float*)d_in[2];
    const float* W2 = (const float*)d_in[3];
    // d_in[4] = b2 (bias does not affect the Jacobian)
    // d_in[5], d_in[6] = create_graph / strict flags (ignored)
    (void)in_sizes; (void)n_in;

    float* out = (float*)d_out;

    // 1) Zero the full [B, DOUT, B, DIN] output
    int n4 = out_size / 4;  // out_size = 16*512*16*512, divisible by 4
    zero_kernel<<<(n4 + 255) / 256, 256>>>((float4*)out, n4);

    // 2) Masks + compacted active-index lists
    mask_compact_kernel<<<BB, 256>>>(x, W1, b1);

    // 3) W1 transpose for coalesced gathers
    transpose_kernel<<<dim3(DH / 32, DIN / 32), dim3(32, 8)>>>(W1);

    // 4) Batched compacted GEMM into diagonal blocks
    gemm_kernel<<<dim3(DIN / 64, DOUT / 64, BB), 256>>>(W2, out);
}

// round 5
// speedup vs baseline: 1.0074x; 1.0074x over previous
#include <cuda_runtime.h>

// Problem constants
#define BB   16
#define DIN  512
#define DH   2048
#define DOUT 512

// Device-global scratch (no allocations allowed in kernel_launch)
__device__ float g_W1T[DH * DIN];   // 4 MB: W1 transposed -> W1T[h][i]
__device__ int   g_act[BB * DH];    // compacted active h indices per batch (sorted)
__device__ int   g_cnt[BB];         // active count per batch

// ---------------------------------------------------------------------------
// Kernel 1: zero the whole output (block-diagonal -> off-diagonal stays 0)
// ---------------------------------------------------------------------------
__global__ void zero_kernel(float4* __restrict__ out, int n4) {
    int idx = blockIdx.x * blockDim.x + threadIdx.x;
    if (idx < n4) out[idx] = make_float4(0.f, 0.f, 0.f, 0.f);
}

// ---------------------------------------------------------------------------
// Kernel 2: per-batch pre-activations, ReLU mask, deterministic compaction.
// One block per b, 256 threads; thread t owns h in [t*8, t*8+8) so the
// compacted index list comes out sorted (deterministic GEMM sum order).
// ---------------------------------------------------------------------------
__global__ void __launch_bounds__(256)
mask_compact_kernel(const float* __restrict__ x,
                    const float* __restrict__ W1,
                    const float* __restrict__ b1) {
    int b = blockIdx.x;
    int t = threadIdx.x;

    __shared__ float xs[DIN];
    for (int i = t; i < DIN; i += 256) xs[i] = x[b * DIN + i];
    __syncthreads();

    const int h0 = t * 8;
    float acc[8];
#pragma unroll
    for (int u = 0; u < 8; u++) acc[u] = b1[h0 + u];

    // Each thread reads a contiguous 32B (2x float4) slice of every W1 row:
    // lane t covers bytes [t*32, t*32+32) -> fully coalesced per warp.
    const float4* wrow = reinterpret_cast<const float4*>(W1 + h0);
    for (int i = 0; i < DIN; i++) {
        float  xv = xs[i];
        float4 w0 = wrow[0];
        float4 w1 = wrow[1];
        wrow += DH / 4;
        acc[0] += xv * w0.x; acc[1] += xv * w0.y;
        acc[2] += xv * w0.z; acc[3] += xv * w0.w;
        acc[4] += xv * w1.x; acc[5] += xv * w1.y;
        acc[6] += xv * w1.z; acc[7] += xv * w1.w;
    }

    int flags = 0, cnt = 0;
#pragma unroll
    for (int u = 0; u < 8; u++) {
        if (acc[u] > 0.f) { flags |= (1 << u); cnt++; }
    }

    // Block-wide inclusive scan (Hillis-Steele) of per-thread counts
    __shared__ int cnts[256];
    cnts[t] = cnt;
    __syncthreads();
    for (int off = 1; off < 256; off <<= 1) {
        int v   = cnts[t];
        int add = (t >= off) ? cnts[t - off] : 0;
        __syncthreads();
        cnts[t] = v + add;
        __syncthreads();
    }

    int pos = cnts[t] - cnt;  // exclusive prefix
#pragma unroll
    for (int u = 0; u < 8; u++) {
        if (flags & (1 << u)) g_act[b * DH + (pos++)] = h0 + u;
    }
    if (t == 255) g_cnt[b] = cnts[255];
}

// ---------------------------------------------------------------------------
// Kernel 3: transpose W1 [DIN, DH] -> g_W1T [DH, DIN] (coalesced gathers later)
// ---------------------------------------------------------------------------
__global__ void transpose_kernel(const float* __restrict__ W1) {
    __shared__ float tile[32][33];
    int h0 = blockIdx.x * 32;
    int i0 = blockIdx.y * 32;
    int tx = threadIdx.x, ty = threadIdx.y;  // 32 x 8
#pragma unroll
    for (int r = 0; r < 32; r += 8)
        tile[ty + r][tx] = W1[(i0 + ty + r) * DH + h0 + tx];
    __syncthreads();
#pragma unroll
    for (int r = 0; r < 32; r += 8)
        g_W1T[(h0 + ty + r) * DIN + i0 + tx] = tile[tx][ty + r];
}

// ---------------------------------------------------------------------------
// Kernel 4: batched compacted GEMM.
//   J[b, o, b, i] = sum_j W2[act[j], o] * W1T[act[j], i]    (j < cnt[b])
// 64x64 output tile per block, 4x4 microtile per thread, K-tile = 16.
// Grid: (i-tiles=8, o-tiles=8, b=16), 256 threads.
// ---------------------------------------------------------------------------
__global__ void __launch_bounds__(256)
gemm_kernel(const float* __restrict__ W2, float* __restrict__ out) {
    int b      = blockIdx.z;
    int tile_o = blockIdx.y * 64;
    int tile_i = blockIdx.x * 64;
    int cnt    = g_cnt[b];
    const int* __restrict__ act = g_act + b * DH;

    __shared__ float As[16][64];  // W2 gathered rows  (k x o)
    __shared__ float Bs[16][64];  // W1T gathered rows (k x i)

    int t  = threadIdx.x;
    int tx = t & 15;   // i direction
    int ty = t >> 4;   // o direction

    float c[4][4] = {};

    for (int kt = 0; kt < cnt; kt += 16) {
        // Fill both tiles: 1024 elems each, 4 per thread
#pragma unroll
        for (int p = 0; p < 4; p++) {
            int e   = t + p * 256;
            int row = e >> 6;
            int col = e & 63;
            int j   = kt + row;
            float av = 0.f, bv = 0.f;
            if (j < cnt) {
                int h = act[j];
                av = W2[h * DOUT + tile_o + col];
                bv = g_W1T[h * DIN + tile_i + col];
            }
            As[row][col] = av;
            Bs[row][col] = bv;
        }
        __syncthreads();

#pragma unroll
        for (int k = 0; k < 16; k++) {
            float4 a = *reinterpret_cast<const float4*>(&As[k][ty * 4]);
            float4 v = *reinterpret_cast<const float4*>(&Bs[k][tx * 4]);
            float ar[4] = {a.x, a.y, a.z, a.w};
            float br[4] = {v.x, v.y, v.z, v.w};
#pragma unroll
            for (int r = 0; r < 4; r++)
#pragma unroll
                for (int s = 0; s < 4; s++)
                    c[r][s] += ar[r] * br[s];
        }
        __syncthreads();
    }

    // Epilogue: write diagonal block J[b, o, b, i]
#pragma unroll
    for (int r = 0; r < 4; r++) {
        int o = tile_o + ty * 4 + r;
        size_t base = ((size_t)((b * DOUT + o) * BB + b)) * DIN + tile_i + tx * 4;
        *reinterpret_cast<float4*>(&out[base]) =
            make_float4(c[r][0], c[r][1], c[r][2], c[r][3]);
    }
}

// ---------------------------------------------------------------------------
// Launch
// ---------------------------------------------------------------------------
extern "C" void kernel_launch(void* const* d_in, const int* in_sizes, int n_in,
                              void* d_out, int out_size) {
    const float* x  = (const float*)d_in[0];
    const float* W1 = (const float*)d_in[1];
    const float* b1 = (const float*)d_in[2];
    const float* W2 = (const float*)d_in[3];
    // d_in[4] = b2 (bias does not affect the Jacobian)
    // d_in[5], d_in[6] = create_graph / strict flags (ignored)
    (void)in_sizes; (void)n_in;

    float* out = (float*)d_out;

    // 1) Zero the full [B, DOUT, B, DIN] output
    int n4 = out_size / 4;  // out_size = 16*512*16*512, divisible by 4
    zero_kernel<<<(n4 + 255) / 256, 256>>>((float4*)out, n4);

    // 2) Masks + compacted active-index lists
    mask_compact_kernel<<<BB, 256>>>(x, W1, b1);

    // 3) W1 transpose for coalesced gathers
    transpose_kernel<<<dim3(DH / 32, DIN / 32), dim3(32, 8)>>>(W1);

    // 4) Batched compacted GEMM into diagonal blocks
    gemm_kernel<<<dim3(DIN / 64, DOUT / 64, BB), 256>>>(W2, out);
}